// round 15
// baseline (speedup 1.0000x reference)
#include <cuda_runtime.h>
#include <math.h>

// ---------------- problem constants ----------------
#define Bq 256
#define Tq 4096
#define Nn 8
#define TWO_N 16
#define Hh 64
#define Pp 144
#define Mi 128              // interpolation intervals over [0,1)
#define RSTRIDE 68          // floats per table row (64 + 4 pad) -> bank rotation
#define NMAIN 4096          // 4096 CTAs x 256 thr x 1 pt
#define NSUP 64

__device__ float g_part[2 * NMAIN];    // [0:4096) data, [4096:8192) physics
__device__ float g_sup[NSUP];
__device__ float g_nodes[(Mi + 1) * 32];              // [node][j]: j<16 latent(+b2), j>=16 dlatent
__device__ __align__(16) float g_table[Mi * RSTRIDE]; // row i: [f_i(32) | f_{i+1}-f_i(32) | pad4]

// ---------------- table build: exact MLP at Mi+1 nodes ----------------
__global__ __launch_bounds__(256)
void pinn_table_nodes(const float* __restrict__ W1,
                      const float* __restrict__ b1,
                      const float* __restrict__ W2,
                      const float* __restrict__ b2)
{
    int idx = blockIdx.x * 256 + threadIdx.x;       // (node, j)
    if (idx >= (Mi + 1) * 32) return;
    int node = idx >> 5;
    int j    = idx & 31;
    float tt = (float)node * (1.0f / (float)Mi);
    bool isLat = (j < TWO_N);
    int jj = isLat ? j : (j - TWO_N);
    float acc = isLat ? b2[jj] : 0.0f;
    for (int k = 0; k < Hh; k++) {
        float a = W1[k];
        float h = tanhf(fmaf(tt, a, b1[k]));
        float w = W2[k * TWO_N + jj];
        if (isLat) acc = fmaf(h, w, acc);
        else       acc = fmaf((1.0f - h * h) * a, w, acc);
    }
    g_nodes[node * 32 + j] = acc;
}

__global__ __launch_bounds__(256)
void pinn_table_rows()
{
    int idx = blockIdx.x * 256 + threadIdx.x;       // (interval, j)
    if (idx >= Mi * 32) return;
    int i = idx >> 5;
    int j = idx & 31;
    float f0 = g_nodes[i * 32 + j];
    float f1 = g_nodes[(i + 1) * 32 + j];
    g_table[i * RSTRIDE + j]      = f0;
    g_table[i * RSTRIDE + 32 + j] = f1 - f0;
}

// ---------------- main kernel: smem table interpolate + losses ----------------
__global__ __launch_bounds__(256, 2)
void pinn_main(const float* __restrict__ t,
               const float* __restrict__ x_target,
               const float* __restrict__ params_pred)
{
    __shared__ __align__(16) float sTab[Mi * RSTRIDE];  // 34.8 KB
    __shared__ float  sPar[Pp];        // g[0:8) mu[8:16) Pi[16:80) Gamma[80:144)
    __shared__ float2 red[256];

    const int tid = threadIdx.x;
    const int b   = blockIdx.x >> 4;                  // 16 chunks per batch
    const int ti  = ((blockIdx.x & 15) << 8) | tid;   // t index in [0,4096)

    // stage table (float4 copy; Mi*RSTRIDE = 8704 floats = 2176 float4)
    {
        const float4* src = (const float4*)g_table;
        float4*       dst = (float4*)sTab;
        #pragma unroll
        for (int i = 0; i < 8; i++) dst[tid + 256 * i] = src[tid + 256 * i];
        if (tid < 128) dst[tid + 2048] = src[tid + 2048];
    }
    if (tid < Pp) sPar[tid] = params_pred[(size_t)b * Pp + tid];
    __syncthreads();

    const float tv = t[(size_t)b * Tq + ti];

    // interval + fraction
    float u  = tv * (float)Mi;
    int   ix = (int)u;
    ix = ix < (Mi - 1) ? ix : (Mi - 1);
    ix = ix > 0 ? ix : 0;
    float frac = u - (float)ix;

    // interpolate 32 values from smem row (8 float4 vals + 8 float4 deltas)
    const float4* row = (const float4*)(sTab + ix * RSTRIDE);
    float s[32];
    #pragma unroll
    for (int q = 0; q < 8; q++) {
        float4 v = row[q];
        float4 d = row[8 + q];
        s[4 * q]     = fmaf(frac, d.x, v.x);
        s[4 * q + 1] = fmaf(frac, d.y, v.y);
        s[4 * q + 2] = fmaf(frac, d.z, v.z);
        s[4 * q + 3] = fmaf(frac, d.w, v.w);
    }
    // s[0..15] = latent (incl b2), s[16..31] = dlatent

    // x_target loads (coalesced)
    const float* xt = x_target + ((size_t)b * TWO_N) * Tq + ti;
    float xtv[TWO_N];
    #pragma unroll
    for (int j = 0; j < TWO_N; j++) xtv[j] = xt[j * Tq];

    // observables + relu JVP
    float av[Nn], xv[Nn], dsa[Nn], dsx[Nn];
    #pragma unroll
    for (int i = 0; i < Nn; i++) {
        av[i]  = s[i];
        dsa[i] = s[TWO_N + i];
        float qm = s[Nn + i] - sPar[Nn + i];          // q - mu
        bool pos = qm > 0.0f;
        xv[i]  = pos ? qm : 0.0f;
        dsx[i] = pos ? s[TWO_N + Nn + i] : 0.0f;
    }

    // data loss
    float dacc = 0.f;
    #pragma unroll
    for (int j = 0; j < Nn; j++) { float d = av[j] - xtv[j];      dacc = fmaf(d, d, dacc); }
    #pragma unroll
    for (int j = 0; j < Nn; j++) { float d = xv[j] - xtv[Nn + j]; dacc = fmaf(d, d, dacc); }

    // physics loss
    float pacc = 0.f;
    #pragma unroll
    for (int i = 0; i < Nn; i++) {
        float da = sPar[i] - av[i];                                               // g - a
        #pragma unroll
        for (int j = 0; j < Nn; j++) da = fmaf(sPar[16 + i * 8 + j], xv[j], da);  // + Pi@x
        float gm = 0.f;
        #pragma unroll
        for (int j = 0; j < Nn; j++) gm = fmaf(sPar[80 + i * 8 + j], av[j], gm);  // Gamma@a
        float dx = gm * (sPar[Nn + i] - xv[i]);                                   // * (mu - x)
        float e1 = dsa[i] - da;
        float e2 = dsx[i] - dx;
        pacc = fmaf(e1, e1, fmaf(e2, e2, pacc));
    }

    // deterministic block tree reduction
    red[tid] = make_float2(dacc, pacc);
    __syncthreads();
    #pragma unroll
    for (int stp = 128; stp > 0; stp >>= 1) {
        if (tid < stp) {
            red[tid].x += red[tid + stp].x;
            red[tid].y += red[tid + stp].y;
        }
        __syncthreads();
    }
    if (tid == 0) {
        g_part[blockIdx.x]         = red[0].x;
        g_part[NMAIN + blockIdx.x] = red[0].y;
    }
}

// ---------------- supervised-loss partials ----------------
__global__ __launch_bounds__(256)
void pinn_sup(const float* __restrict__ params_pred,
              const float* __restrict__ params_target,
              const float* __restrict__ ic_pred,
              const float* __restrict__ ic_target)
{
    __shared__ float ss[256];
    const int tid = threadIdx.x;
    const int g0  = blockIdx.x * 256 + tid;
    float sup = 0.f;
    for (int i = g0; i < Bq * Pp; i += NSUP * 256) {
        float e = params_pred[i] - params_target[i];
        sup = fmaf(e, e, sup);
    }
    for (int i = g0; i < Bq * TWO_N; i += NSUP * 256) {
        float e = ic_pred[i] - ic_target[i];
        sup = fmaf(e, e, sup);
    }
    ss[tid] = sup;
    __syncthreads();
    #pragma unroll
    for (int stp = 128; stp > 0; stp >>= 1) {
        if (tid < stp) ss[tid] += ss[tid + stp];
        __syncthreads();
    }
    if (tid == 0) g_sup[blockIdx.x] = ss[0];
}

// ---------------- final combine ----------------
__global__ __launch_bounds__(1024)
void pinn_final(float* __restrict__ out)
{
    __shared__ float sd[1024], sp[1024], ss[1024];
    const int tid = threadIdx.x;
    float d = 0.f, p = 0.f, s = 0.f;
    for (int i = tid; i < NMAIN; i += 1024) {
        d += g_part[i];
        p += g_part[NMAIN + i];
    }
    if (tid < NSUP) s = g_sup[tid];
    sd[tid] = d; sp[tid] = p; ss[tid] = s;
    __syncthreads();
    #pragma unroll
    for (int stp = 512; stp > 0; stp >>= 1) {
        if (tid < stp) {
            sd[tid] += sd[tid + stp];
            sp[tid] += sp[tid + stp];
            ss[tid] += ss[tid + stp];
        }
        __syncthreads();
    }
    if (tid == 0) {
        const float inv_dp = 1.0f / 16777216.0f;   // B * 2N * T
        const float inv_s  = 1.0f / 40960.0f;      // B * (P + 2N)
        out[0] = (sd[0] + sp[0]) * inv_dp + ss[0] * inv_s;
    }
}

extern "C" void kernel_launch(void* const* d_in, const int* in_sizes, int n_in,
                              void* d_out, int out_size)
{
    const float* t             = (const float*)d_in[0];
    const float* x_target      = (const float*)d_in[1];
    const float* params_pred   = (const float*)d_in[2];
    const float* params_target = (const float*)d_in[3];
    const float* ic_pred       = (const float*)d_in[4];
    const float* ic_target     = (const float*)d_in[5];
    const float* W1            = (const float*)d_in[6];
    const float* b1            = (const float*)d_in[7];
    const float* W2            = (const float*)d_in[8];
    const float* b2            = (const float*)d_in[9];
    float* out = (float*)d_out;

    pinn_table_nodes<<<((Mi + 1) * 32 + 255) / 256, 256>>>(W1, b1, W2, b2);
    pinn_table_rows<<<(Mi * 32 + 255) / 256, 256>>>();
    pinn_sup<<<NSUP, 256>>>(params_pred, params_target, ic_pred, ic_target);
    pinn_main<<<NMAIN, 256>>>(t, x_target, params_pred);
    pinn_final<<<1, 1024>>>(out);
}

// round 16
// speedup vs baseline: 1.7500x; 1.7500x over previous
#include <cuda_runtime.h>
#include <cuda_bf16.h>
#include <math.h>

// ---------------- problem constants ----------------
#define Bq 256
#define Tq 4096
#define Nn 8
#define TWO_N 16
#define Hh 64
#define Pp 144
#define Mi 128              // interpolation intervals over [0,1)
#define RSTRIDE 52          // u32 words per row: 32 val + 16 delta(bf16x2) + 4 pad
#define NMAIN 4096          // 4096 CTAs x 256 thr x 1 pt
#define NSUP 64

__device__ float g_part[2 * NMAIN];    // [0:4096) data, [4096:8192) physics
__device__ float g_sup[NSUP];
__device__ float g_nodes[(Mi + 1) * 32];              // [node][j]: j<16 latent(+b2), j>=16 dlatent
__device__ __align__(16) unsigned g_table[Mi * RSTRIDE];

// ---------------- table build: exact MLP at Mi+1 nodes ----------------
__global__ __launch_bounds__(256)
void pinn_table_nodes(const float* __restrict__ W1,
                      const float* __restrict__ b1,
                      const float* __restrict__ W2,
                      const float* __restrict__ b2)
{
    int idx = blockIdx.x * 256 + threadIdx.x;       // (node, j)
    if (idx >= (Mi + 1) * 32) return;
    int node = idx >> 5;
    int j    = idx & 31;
    float tt = (float)node * (1.0f / (float)Mi);
    bool isLat = (j < TWO_N);
    int jj = isLat ? j : (j - TWO_N);
    float acc = isLat ? b2[jj] : 0.0f;
    for (int k = 0; k < Hh; k++) {
        float a = W1[k];
        float h = tanhf(fmaf(tt, a, b1[k]));
        float w = W2[k * TWO_N + jj];
        if (isLat) acc = fmaf(h, w, acc);
        else       acc = fmaf((1.0f - h * h) * a, w, acc);
    }
    g_nodes[node * 32 + j] = acc;
}

__global__ __launch_bounds__(256)
void pinn_table_rows()
{
    int idx = blockIdx.x * 256 + threadIdx.x;       // (interval, slot) slot in [0,48)
    if (idx >= Mi * 48) return;
    int i = idx / 48;
    int sl = idx - i * 48;
    if (sl < 32) {
        // value word: f_i[sl]
        g_table[i * RSTRIDE + sl] = __float_as_uint(g_nodes[i * 32 + sl]);
    } else {
        // delta pair jj: (f_{i+1}-f_i)[2jj], [2jj+1] packed bf16x2
        int jj = sl - 32;
        float d0 = g_nodes[(i + 1) * 32 + 2 * jj]     - g_nodes[i * 32 + 2 * jj];
        float d1 = g_nodes[(i + 1) * 32 + 2 * jj + 1] - g_nodes[i * 32 + 2 * jj + 1];
        __nv_bfloat162 p = __floats2bfloat162_rn(d0, d1);
        g_table[i * RSTRIDE + 32 + jj] = *reinterpret_cast<unsigned*>(&p);
    }
}

// unpack helpers
__device__ __forceinline__ void bf2_unpack(unsigned w, float &lo, float &hi) {
    __nv_bfloat162 h = *reinterpret_cast<__nv_bfloat162*>(&w);
    lo = __low2float(h);
    hi = __high2float(h);
}

// ---------------- main kernel: smem table interpolate + losses, 3 CTAs/SM ----------------
__global__ __launch_bounds__(256, 3)
void pinn_main(const float* __restrict__ t,
               const float* __restrict__ x_target,
               const float* __restrict__ params_pred)
{
    __shared__ __align__(16) unsigned sTab[Mi * RSTRIDE];  // 26.6 KB
    __shared__ float  sPar[Pp];        // g[0:8) mu[8:16) Pi[16:80) Gamma[80:144)
    __shared__ float2 red[256];

    const int tid = threadIdx.x;
    const int b   = blockIdx.x >> 4;                  // 16 chunks per batch
    const int ti  = ((blockIdx.x & 15) << 8) | tid;   // t index in [0,4096)

    // stage table flat (Mi*RSTRIDE = 6656 words = 1664 uint4)
    {
        const uint4* src = (const uint4*)g_table;
        uint4*       dst = (uint4*)sTab;
        #pragma unroll
        for (int i = 0; i < 6; i++) dst[tid + 256 * i] = src[tid + 256 * i];
        if (tid < 128) dst[tid + 1536] = src[tid + 1536];
    }
    if (tid < Pp) sPar[tid] = params_pred[(size_t)b * Pp + tid];

    // t load + x_target prefetch issued before table use (hide DRAM latency)
    const float tv = t[(size_t)b * Tq + ti];
    const float* xt = x_target + ((size_t)b * TWO_N) * Tq + ti;
    float xtv[TWO_N];
    #pragma unroll
    for (int j = 0; j < TWO_N; j++) xtv[j] = xt[j * Tq];

    __syncthreads();

    // interval + fraction
    float u  = tv * (float)Mi;
    int   ix = (int)u;
    ix = ix < (Mi - 1) ? ix : (Mi - 1);
    ix = ix > 0 ? ix : 0;
    float frac = u - (float)ix;

    const uint4* row  = (const uint4*)(sTab + ix * RSTRIDE);        // value chunks 0..7
    const uint4* rowd = (const uint4*)(sTab + ix * RSTRIDE + 32);   // delta chunks 0..3

    // ---------- phase 1: latent (j 0..15) -> av, xv, data loss ----------
    float av[Nn], xv[Nn];
    float dacc = 0.f;
    {
        float s[TWO_N];
        #pragma unroll
        for (int q = 0; q < 4; q++) {                 // value chunks 0..3 (j 0..15)
            uint4 vv = row[q];
            uint4 dw = rowd[q >> 1];                  // delta chunk q/2 covers 8 j
            unsigned dsel0 = (q & 1) ? dw.z : dw.x;
            unsigned dsel1 = (q & 1) ? dw.w : dw.y;
            float d0, d1, d2, d3;
            bf2_unpack(dsel0, d0, d1);
            bf2_unpack(dsel1, d2, d3);
            s[4 * q]     = fmaf(frac, d0, __uint_as_float(vv.x));
            s[4 * q + 1] = fmaf(frac, d1, __uint_as_float(vv.y));
            s[4 * q + 2] = fmaf(frac, d2, __uint_as_float(vv.z));
            s[4 * q + 3] = fmaf(frac, d3, __uint_as_float(vv.w));
        }
        #pragma unroll
        for (int i = 0; i < Nn; i++) {
            av[i] = s[i];
            float qm = s[Nn + i] - sPar[Nn + i];      // q - mu
            xv[i] = qm > 0.0f ? qm : 0.0f;
        }
        #pragma unroll
        for (int j = 0; j < Nn; j++) { float d = av[j] - xtv[j];      dacc = fmaf(d, d, dacc); }
        #pragma unroll
        for (int j = 0; j < Nn; j++) { float d = xv[j] - xtv[Nn + j]; dacc = fmaf(d, d, dacc); }
    }

    // ---------- phase 2: dlatent (j 16..31) -> physics loss ----------
    float pacc = 0.f;
    {
        float ds[TWO_N];
        #pragma unroll
        for (int q = 0; q < 4; q++) {                 // value chunks 4..7
            uint4 vv = row[4 + q];
            uint4 dw = rowd[2 + (q >> 1)];
            unsigned dsel0 = (q & 1) ? dw.z : dw.x;
            unsigned dsel1 = (q & 1) ? dw.w : dw.y;
            float d0, d1, d2, d3;
            bf2_unpack(dsel0, d0, d1);
            bf2_unpack(dsel1, d2, d3);
            ds[4 * q]     = fmaf(frac, d0, __uint_as_float(vv.x));
            ds[4 * q + 1] = fmaf(frac, d1, __uint_as_float(vv.y));
            ds[4 * q + 2] = fmaf(frac, d2, __uint_as_float(vv.z));
            ds[4 * q + 3] = fmaf(frac, d3, __uint_as_float(vv.w));
        }
        #pragma unroll
        for (int i = 0; i < Nn; i++) {
            float dsa = ds[i];
            float dsx = xv[i] > 0.0f ? ds[Nn + i] : 0.0f;
            float da = sPar[i] - av[i];                                               // g - a
            #pragma unroll
            for (int j = 0; j < Nn; j++) da = fmaf(sPar[16 + i * 8 + j], xv[j], da);  // + Pi@x
            float gm = 0.f;
            #pragma unroll
            for (int j = 0; j < Nn; j++) gm = fmaf(sPar[80 + i * 8 + j], av[j], gm);  // Gamma@a
            float dx = gm * (sPar[Nn + i] - xv[i]);                                   // * (mu - x)
            float e1 = dsa - da;
            float e2 = dsx - dx;
            pacc = fmaf(e1, e1, fmaf(e2, e2, pacc));
        }
    }

    // deterministic block tree reduction
    red[tid] = make_float2(dacc, pacc);
    __syncthreads();
    #pragma unroll
    for (int stp = 128; stp > 0; stp >>= 1) {
        if (tid < stp) {
            red[tid].x += red[tid + stp].x;
            red[tid].y += red[tid + stp].y;
        }
        __syncthreads();
    }
    if (tid == 0) {
        g_part[blockIdx.x]         = red[0].x;
        g_part[NMAIN + blockIdx.x] = red[0].y;
    }
}

// ---------------- supervised-loss partials ----------------
__global__ __launch_bounds__(256)
void pinn_sup(const float* __restrict__ params_pred,
              const float* __restrict__ params_target,
              const float* __restrict__ ic_pred,
              const float* __restrict__ ic_target)
{
    __shared__ float ss[256];
    const int tid = threadIdx.x;
    const int g0  = blockIdx.x * 256 + tid;
    float sup = 0.f;
    for (int i = g0; i < Bq * Pp; i += NSUP * 256) {
        float e = params_pred[i] - params_target[i];
        sup = fmaf(e, e, sup);
    }
    for (int i = g0; i < Bq * TWO_N; i += NSUP * 256) {
        float e = ic_pred[i] - ic_target[i];
        sup = fmaf(e, e, sup);
    }
    ss[tid] = sup;
    __syncthreads();
    #pragma unroll
    for (int stp = 128; stp > 0; stp >>= 1) {
        if (tid < stp) ss[tid] += ss[tid + stp];
        __syncthreads();
    }
    if (tid == 0) g_sup[blockIdx.x] = ss[0];
}

// ---------------- final combine ----------------
__global__ __launch_bounds__(1024)
void pinn_final(float* __restrict__ out)
{
    __shared__ float sd[1024], sp[1024], ss[1024];
    const int tid = threadIdx.x;
    float d = 0.f, p = 0.f, s = 0.f;
    for (int i = tid; i < NMAIN; i += 1024) {
        d += g_part[i];
        p += g_part[NMAIN + i];
    }
    if (tid < NSUP) s = g_sup[tid];
    sd[tid] = d; sp[tid] = p; ss[tid] = s;
    __syncthreads();
    #pragma unroll
    for (int stp = 512; stp > 0; stp >>= 1) {
        if (tid < stp) {
            sd[tid] += sd[tid + stp];
            sp[tid] += sp[tid + stp];
            ss[tid] += ss[tid + stp];
        }
        __syncthreads();
    }
    if (tid == 0) {
        const float inv_dp = 1.0f / 16777216.0f;   // B * 2N * T
        const float inv_s  = 1.0f / 40960.0f;      // B * (P + 2N)
        out[0] = (sd[0] + sp[0]) * inv_dp + ss[0] * inv_s;
    }
}

extern "C" void kernel_launch(void* const* d_in, const int* in_sizes, int n_in,
                              void* d_out, int out_size)
{
    const float* t             = (const float*)d_in[0];
    const float* x_target      = (const float*)d_in[1];
    const float* params_pred   = (const float*)d_in[2];
    const float* params_target = (const float*)d_in[3];
    const float* ic_pred       = (const float*)d_in[4];
    const float* ic_target     = (const float*)d_in[5];
    const float* W1            = (const float*)d_in[6];
    const float* b1            = (const float*)d_in[7];
    const float* W2            = (const float*)d_in[8];
    const float* b2            = (const float*)d_in[9];
    float* out = (float*)d_out;

    pinn_table_nodes<<<((Mi + 1) * 32 + 255) / 256, 256>>>(W1, b1, W2, b2);
    pinn_table_rows<<<(Mi * 48 + 255) / 256, 256>>>();
    pinn_sup<<<NSUP, 256>>>(params_pred, params_target, ic_pred, ic_target);
    pinn_main<<<NMAIN, 256>>>(t, x_target, params_pred);
    pinn_final<<<1, 1024>>>(out);
}